// round 15
// baseline (speedup 1.0000x reference)
#include <cuda_runtime.h>
#include <cuda_fp16.h>
#include <cstdint>

// Problem constants (fixed by setup_inputs)
#define B_   16
#define N_   1024
#define C_   768
#define H_   12
#define D_   64
#define M_   (B_*N_)     // 16384
#define QKV_ (3*C_)      // 2304

// ---------------- scratch (device globals: allocation-free) ----------------
__device__ __align__(16) __half g_xh[M_*C_];
__device__ __align__(16) __half g_wqh[QKV_*C_];        // [N,K] rounded
__device__ __align__(16) __half g_wph[C_*C_];          // [N,K] rounded
__device__ __align__(16) __half g_qh[B_*H_*N_*D_];
__device__ __align__(16) __half g_kh[B_*H_*N_*D_];
__device__ __align__(16) __half g_vh[B_*H_*N_*D_];
__device__ __align__(16) __half g_oh[M_*C_];

// ================= low-level helpers =================
__device__ __forceinline__ uint32_t smem_u32(const void* p) {
    uint32_t a;
    asm("{ .reg .u64 t; cvta.to.shared.u64 t, %1; cvt.u32.u64 %0, t; }"
        : "=r"(a) : "l"(p));
    return a;
}
__device__ __forceinline__ uint32_t sw128(uint32_t off) {
    return off ^ ((off >> 3) & 0x70);
}
__device__ __forceinline__ uint32_t swbase(uint32_t R) {
    return R ^ ((R >> 3) & 0x70);
}
#define CP_A16(s, g) \
    asm volatile("cp.async.cg.shared.global [%0], [%1], 16;" :: "r"(s), "l"(g) : "memory")
#define CP_COMMIT() asm volatile("cp.async.commit_group;" ::: "memory")
#define CP_WAIT1()  asm volatile("cp.async.wait_group 1;" ::: "memory")
#define CP_WAIT0()  asm volatile("cp.async.wait_group 0;" ::: "memory")

#define LDSM4(r, addr) \
    asm volatile("ldmatrix.sync.aligned.m8n8.x4.shared.b16 {%0,%1,%2,%3}, [%4];" \
        : "=r"((r)[0]), "=r"((r)[1]), "=r"((r)[2]), "=r"((r)[3]) : "r"(addr))
#define LDSM4T(r, addr) \
    asm volatile("ldmatrix.sync.aligned.m8n8.x4.trans.shared.b16 {%0,%1,%2,%3}, [%4];" \
        : "=r"((r)[0]), "=r"((r)[1]), "=r"((r)[2]), "=r"((r)[3]) : "r"(addr))

__device__ __forceinline__ void mma16816(float* c, const uint32_t* a,
                                         uint32_t b0, uint32_t b1) {
    asm volatile(
        "mma.sync.aligned.m16n8k16.row.col.f32.f16.f16.f32 "
        "{%0,%1,%2,%3}, {%4,%5,%6,%7}, {%8,%9}, {%0,%1,%2,%3};"
        : "+f"(c[0]), "+f"(c[1]), "+f"(c[2]), "+f"(c[3])
        : "r"(a[0]), "r"(a[1]), "r"(a[2]), "r"(a[3]), "r"(b0), "r"(b1));
}
__device__ __forceinline__ uint32_t packhf(float a, float b) {
    __half2 h = __floats2half2_rn(a, b);
    return *reinterpret_cast<uint32_t*>(&h);
}

// ---------- packed f32x2 helpers (sm_100+ base ISA) ----------
typedef unsigned long long u64;
__device__ __forceinline__ u64 pk2(float a, float b) {
    u64 r;
    asm("mov.b64 %0, {%1,%2};" : "=l"(r) : "f"(a), "f"(b));
    return r;
}
__device__ __forceinline__ void upk2(u64 p, float& a, float& b) {
    asm("mov.b64 {%0,%1}, %2;" : "=f"(a), "=f"(b) : "l"(p));
}
#define ADD2(d, a, b) asm("add.rn.f32x2 %0, %1, %2;" : "=l"(d) : "l"(a), "l"(b))
#define MUL2(d, a, b) asm("mul.rn.f32x2 %0, %1, %2;" : "=l"(d) : "l"(a), "l"(b))
#define FMA2(d, a, b, c) \
    asm("fma.rn.f32x2 %0, %1, %2, %3;" : "=l"(d) : "l"(a), "l"(b), "l"(c))

// packed exp2 with built-in shift: returns 2^(x - 13) for x in [-12, 12].
// Shift 13 >= Cauchy-Schwarz bound 11.54 folds into the exponent bias (ALU),
// costing zero fma-pipe ops. Degree-4 poly, rel err ~4e-5.
struct ExpC {
    u64 M, NM, C4, C3, C2, C1, C0;
    __device__ __forceinline__ void init() {
        M  = pk2(12582912.0f, 12582912.0f);
        NM = pk2(-12582912.0f, -12582912.0f);
        C4 = pk2(9.6181291e-3f, 9.6181291e-3f);
        C3 = pk2(5.5504109e-2f, 5.5504109e-2f);
        C2 = pk2(2.4022651e-1f, 2.4022651e-1f);
        C1 = pk2(6.9314718e-1f, 6.9314718e-1f);
        C0 = pk2(1.0f, 1.0f);
    }
};
__device__ __forceinline__ u64 exp2s13x2(u64 x, const ExpC& C) {
    u64 z, t, f, p, sc;
    ADD2(z, x, C.M);
    ADD2(t, z, C.NM);
    t ^= 0x8000000080000000ull;
    ADD2(f, x, t);
    p = C.C4;
    FMA2(p, p, f, C.C3);
    FMA2(p, p, f, C.C2);
    FMA2(p, p, f, C.C1);
    FMA2(p, p, f, C.C0);
    uint32_t elo = (uint32_t)z, ehi = (uint32_t)(z >> 32);
    uint32_t slo = (elo << 23) + 0x39000000u;   // bias - (13<<23)
    uint32_t shi = (ehi << 23) + 0x39000000u;
    asm("mov.b64 %0, {%1,%2};" : "=l"(sc) : "r"(slo), "r"(shi));
    MUL2(p, p, sc);
    return p;
}

// ================= fused prep kernel =================
#define XBLK (M_*C_/4/256)       // 12288

__global__ __launch_bounds__(256)
void prep_all(const float4* __restrict__ x, __half* __restrict__ xh,
              const float* __restrict__ wq, __half* __restrict__ wqh,
              const float* __restrict__ wp, __half* __restrict__ wph)
{
    __shared__ float t[32][33];
    const int bx = blockIdx.x;
    if (bx < XBLK) {
        const uint32_t i = bx * 256 + threadIdx.x;
        float4 v = x[i];
        *(__half2*)(xh + 4*(size_t)i)     = __floats2half2_rn(v.x, v.y);
        *(__half2*)(xh + 4*(size_t)i + 2) = __floats2half2_rn(v.z, v.w);
        return;
    }
    const float* W;
    __half* Th;
    int idx, Ndim;
    if (bx < XBLK + 1728) {
        idx = bx - XBLK; W = wq; Th = wqh; Ndim = QKV_;
    } else {
        idx = bx - XBLK - 1728; W = wp; Th = wph; Ndim = C_;
    }
    const int kk = (idx % 24) * 32, nn = (idx / 24) * 32;
    const int tx = threadIdx.x & 31, ty = threadIdx.x >> 5;
    #pragma unroll
    for (int i = ty; i < 32; i += 8)
        t[i][tx] = W[(size_t)(kk + i) * Ndim + nn + tx];
    __syncthreads();
    #pragma unroll
    for (int i = ty; i < 32; i += 8)
        Th[(size_t)(nn + i) * C_ + kk + tx] = __float2half_rn(t[tx][i]);
}

// ================= fp16 HMMA GEMM, 128x256 tiles, 512 threads =============
// 16 warps, warp tile 32x64. 3-stage pipeline, 48 KB/stage, 144 KB smem.
#define GTA 16384                   // A: 128 rows x 128 bytes
#define GTB 32768                   // B: 256 rows x 128 bytes
#define GSTAGE (GTA+GTB)            // 48 KB
#define GEMM_SMEM (3*GSTAGE)        // 147456

template<bool FUSED>
__global__ __launch_bounds__(512, 1)
void gemm_mma(const __half* __restrict__ Ah, const __half* __restrict__ Bh,
              float* __restrict__ Cm, int Mdim, int Ndim, int Kdim,
              const float* __restrict__ bias,
              const float* __restrict__ cosr, const float* __restrict__ sinr,
              const float* __restrict__ qw, const float* __restrict__ qb,
              const float* __restrict__ kw, const float* __restrict__ kb,
              const int* __restrict__ pP, const int* __restrict__ pL,
              __half* __restrict__ Qh,
              __half* __restrict__ Kh, __half* __restrict__ Vh)
{
    extern __shared__ char smem[];
    const uint32_t sb = smem_u32(smem);
    const int tid = threadIdx.x;
    const int wid = tid >> 5, lane = tid & 31;
    const int m0 = blockIdx.y * 128, n0 = blockIdx.x * 256;
    const int wm = (wid & 3) * 32, wn = (wid >> 2) * 64;
    const int nchunks = Kdim / 64;   // 12

    const int r0 = tid >> 3, u8 = tid & 7;      // r0: 0..63
    const __half* pA = Ah + (size_t)(m0 + r0) * Kdim + u8 * 8;
    const __half* pB = Bh + (size_t)(n0 + r0) * Kdim + u8 * 8;
    const uint32_t d0 = sw128((uint32_t)(r0 * 128 + u8 * 16));
    const size_t rstr = (size_t)64 * Kdim;

    auto issue = [&](int c) {
        const uint32_t stg = sb + (uint32_t)(c % 3) * GSTAGE;
        const int k0 = c * 64;
        const __half* a = pA + k0;
        const __half* b = pB + k0;
        #pragma unroll
        for (int t = 0; t < 2; t++)
            CP_A16(stg + d0 + t*8192,
                   (u64)__cvta_generic_to_global(a + t*rstr));
        #pragma unroll
        for (int t = 0; t < 4; t++)
            CP_A16(stg + GTA + d0 + t*8192,
                   (u64)__cvta_generic_to_global(b + t*rstr));
    };

    uint32_t offA[2], offB[4];
    #pragma unroll
    for (int mt = 0; mt < 2; mt++)
        offA[mt] = swbase((uint32_t)((wm + mt*16 + (lane & 15)) * 128)) ^ (lane & 16);
    #pragma unroll
    for (int p = 0; p < 4; p++)
        offB[p] = swbase((uint32_t)((wn + p*16 + (lane & 7) + ((lane & 16) >> 1)) * 128))
                  ^ ((lane & 8) << 1);

    float acc[2][8][4];
    #pragma unroll
    for (int i = 0; i < 2; i++)
        #pragma unroll
        for (int j = 0; j < 8; j++)
            #pragma unroll
            for (int q = 0; q < 4; q++) acc[i][j][q] = 0.f;

    issue(0); CP_COMMIT();
    issue(1); CP_COMMIT();

    for (int c = 0; c < nchunks; c++) {
        if (c == nchunks - 1) { CP_WAIT0(); } else { CP_WAIT1(); }
        __syncthreads();
        if (c + 2 < nchunks) { issue(c + 2); CP_COMMIT(); }

        const uint32_t sAh = sb + (uint32_t)(c % 3) * GSTAGE;
        const uint32_t sBh = sAh + GTA;

        #pragma unroll
        for (int ks = 0; ks < 4; ks++) {
            const uint32_t kx = (uint32_t)(ks << 5);
            uint32_t ah[2][4];
            #pragma unroll
            for (int mt = 0; mt < 2; mt++)
                LDSM4(ah[mt], sAh + (offA[mt] ^ kx));
            uint32_t bh[4][4];
            #pragma unroll
            for (int p = 0; p < 4; p++)
                LDSM4(bh[p], sBh + (offB[p] ^ kx));
            #pragma unroll
            for (int mt = 0; mt < 2; mt++)
                #pragma unroll
                for (int p = 0; p < 4; p++)
                    #pragma unroll
                    for (int h2 = 0; h2 < 2; h2++) {
                        int nt = 2*p + h2;
                        mma16816(acc[mt][nt], ah[mt], bh[p][2*h2], bh[p][2*h2+1]);
                    }
        }
    }

    if (!FUSED) {
        #pragma unroll
        for (int mt = 0; mt < 2; mt++)
            #pragma unroll
            for (int nt = 0; nt < 8; nt++) {
                int row = m0 + wm + mt*16 + (lane >> 2);
                int col = n0 + wn + nt*8 + 2*(lane & 3);
                float b0 = 0.f, b1 = 0.f;
                if (bias) { b0 = bias[col]; b1 = bias[col + 1]; }
                float2 v0 = make_float2(acc[mt][nt][0] + b0, acc[mt][nt][1] + b1);
                float2 v1 = make_float2(acc[mt][nt][2] + b0, acc[mt][nt][3] + b1);
                *(float2*)(Cm + (size_t)row * Ndim + col)       = v0;
                *(float2*)(Cm + (size_t)(row + 8) * Ndim + col) = v1;
            }
    } else {
        const int gcol = n0 + wn;
        const int kind = gcol / C_;             // 0=q, 1=k, 2=v
        const int head = (gcol % C_) / D_;
        const int Pp = __ldg(pP), Ll = __ldg(pL);
        const float* lw = (kind == 0) ? qw : kw;
        const float* lb = (kind == 0) ? qb : kb;
        const float QSC = 0.18033688011112042f; // (1/8)*log2(e)

        #pragma unroll
        for (int mt = 0; mt < 2; mt++) {
            const int m1 = m0 + wm + mt*16 + (lane >> 2);
            const int m2 = m1 + 8;
            const int b1i = m1 >> 10, n1 = m1 & (N_-1);
            const int b2i = m2 >> 10, n2 = m2 & (N_-1);
            const size_t o1 = (((size_t)(b1i*H_ + head))*N_ + n1) * D_;
            const size_t o2 = (((size_t)(b2i*H_ + head))*N_ + n2) * D_;

            if (kind == 2) {
                #pragma unroll
                for (int nt = 0; nt < 8; nt++) {
                    int col = nt*8 + 2*(lane & 3);
                    *(uint32_t*)(Vh + o1 + col) = packhf(acc[mt][nt][0], acc[mt][nt][1]);
                    *(uint32_t*)(Vh + o2 + col) = packhf(acc[mt][nt][2], acc[mt][nt][3]);
                }
            } else {
                float s1 = 0.f, s2 = 0.f;
                #pragma unroll
                for (int nt = 0; nt < 8; nt++) {
                    s1 += acc[mt][nt][0] + acc[mt][nt][1];
                    s2 += acc[mt][nt][2] + acc[mt][nt][3];
                }
                s1 += __shfl_xor_sync(~0u, s1, 1); s1 += __shfl_xor_sync(~0u, s1, 2);
                s2 += __shfl_xor_sync(~0u, s2, 1); s2 += __shfl_xor_sync(~0u, s2, 2);
                const float mu1 = s1 * (1.0f/64.0f), mu2 = s2 * (1.0f/64.0f);
                float v1 = 0.f, v2 = 0.f;
                #pragma unroll
                for (int nt = 0; nt < 8; nt++) {
                    float d0f = acc[mt][nt][0] - mu1, d1f = acc[mt][nt][1] - mu1;
                    float d2f = acc[mt][nt][2] - mu2, d3f = acc[mt][nt][3] - mu2;
                    v1 += d0f*d0f + d1f*d1f;
                    v2 += d2f*d2f + d3f*d3f;
                }
                v1 += __shfl_xor_sync(~0u, v1, 1); v1 += __shfl_xor_sync(~0u, v1, 2);
                v2 += __shfl_xor_sync(~0u, v2, 1); v2 += __shfl_xor_sync(~0u, v2, 2);
                const float iv1 = rsqrtf(v1*(1.0f/64.0f) + 1e-5f);
                const float iv2 = rsqrtf(v2*(1.0f/64.0f) + 1e-5f);
                const bool r1 = (n1 >= Pp) && (n1 < N_ - Ll);
                const bool r2 = (n2 >= Pp) && (n2 < N_ - Ll);

                #pragma unroll
                for (int nt = 0; nt < 8; nt++) {
                    const int col  = nt*8 + 2*(lane & 3);
                    const int colp = nt*4 + (lane & 3);
                    float2 w2 = *(const float2*)(lw + col);
                    float2 bb = *(const float2*)(lb + col);
                    float y0 = fmaf((acc[mt][nt][0]-mu1)*iv1, w2.x, bb.x);
                    float y1 = fmaf((acc[mt][nt][1]-mu1)*iv1, w2.y, bb.y);
                    float y2 = fmaf((acc[mt][nt][2]-mu2)*iv2, w2.x, bb.x);
                    float y3 = fmaf((acc[mt][nt][3]-mu2)*iv2, w2.y, bb.y);
                    if (r1) {
                        float rc = cosr[(n1-Pp)*32 + colp], rs = sinr[(n1-Pp)*32 + colp];
                        float t0 = y0*rc - y1*rs, t1 = y0*rs + y1*rc;
                        y0 = t0; y1 = t1;
                    }
                    if (r2) {
                        float rc = cosr[(n2-Pp)*32 + colp], rs = sinr[(n2-Pp)*32 + colp];
                        float t2 = y2*rc - y3*rs, t3 = y2*rs + y3*rc;
                        y2 = t2; y3 = t3;
                    }
                    if (kind == 0) {
                        y0 *= QSC; y1 *= QSC; y2 *= QSC; y3 *= QSC;
                        *(uint32_t*)(Qh + o1 + col) = packhf(y0, y1);
                        *(uint32_t*)(Qh + o2 + col) = packhf(y2, y3);
                    } else {
                        *(uint32_t*)(Kh + o1 + col) = packhf(y0, y1);
                        *(uint32_t*)(Kh + o2 + col) = packhf(y2, y3);
                    }
                }
            }
        }
    }
}

// ================= HMMA flash attention (fixed-shift softmax) =============
// |S_log2| <= 11.54 (Cauchy-Schwarz after LN); p = 2^(s-13) via exp2s13x2.
#define KTILE2 16384                  // 128 rows x 128 bytes
#define ASTAGE (2*KTILE2)             // Kh,Vh = 32 KB
#define ATT_SMEM (3*ASTAGE)           // 98304

__global__ __launch_bounds__(256, 2)
void attn_mma(const __half* __restrict__ Qh,
              const __half* __restrict__ Kh, const __half* __restrict__ Vh,
              __half* __restrict__ Oh)
{
    extern __shared__ char smem[];
    const uint32_t sb = smem_u32(smem);
    const int tid = threadIdx.x;
    const int wid = tid >> 5, lane = tid & 31;
    const int b = blockIdx.z, h = blockIdx.y;
    const int q0 = blockIdx.x * 128;
    const size_t base = ((size_t)(b*H_ + h)) * N_;

    ExpC EC; EC.init();

    const int r0 = tid >> 3, u8 = tid & 7;
    const uint32_t d0 = sw128((uint32_t)(r0 * 128 + u8 * 16));
    const __half* pK = Kh + (base + r0) * D_ + u8 * 8;
    const __half* pV = Vh + (base + r0) * D_ + u8 * 8;

    // ---- stage Q tile (16 KB, in stage-0 area) ----
    {
        const __half* pQ = Qh + (base + q0 + r0) * D_ + u8 * 8;
        #pragma unroll
        for (int t = 0; t < 4; t++) {
            uint4 v = *(const uint4*)(pQ + t * 32 * D_);
            *(uint4*)(smem + d0 + t*4096) = v;
        }
    }
    __syncthreads();

    uint32_t qh[4][4];
    {
        const uint32_t offQ = swbase((uint32_t)((wid*16 + (lane & 15)) * 128)) ^ (lane & 16);
        #pragma unroll
        for (int ks = 0; ks < 4; ks++)
            LDSM4(qh[ks], sb + (offQ ^ (uint32_t)(ks << 5)));
    }
    __syncthreads();   // Q reads done; smem reusable for KV stages

    uint32_t offK[4], offV[4];
    #pragma unroll
    for (int p = 0; p < 4; p++)
        offK[p] = swbase((uint32_t)((p*16 + (lane & 7) + ((lane & 16) >> 1)) * 128))
                  ^ ((lane & 8) << 1);
    #pragma unroll
    for (int ds = 0; ds < 4; ds++)
        offV[ds] = swbase((uint32_t)((ds*16 + (lane & 15)) * 128)) ^ (lane & 16);

    auto issue = [&](int kt) {
        const uint32_t stg = sb + (uint32_t)(kt % 3) * ASTAGE;
        const int koff = kt * 128 * D_;
        const __half* k = pK + koff;
        const __half* v = pV + koff;
        #pragma unroll
        for (int t = 0; t < 4; t++) {
            CP_A16(stg + d0 + t*4096,
                   (u64)__cvta_generic_to_global(k + t * 32 * D_));
            CP_A16(stg + KTILE2 + d0 + t*4096,
                   (u64)__cvta_generic_to_global(v + t * 32 * D_));
        }
    };

    float o[8][4];
    #pragma unroll
    for (int j = 0; j < 8; j++)
        #pragma unroll
        for (int q = 0; q < 4; q++) o[j][q] = 0.f;
    u64 ls0 = 0ull, ls1 = 0ull;            // packed li accumulators

    issue(0); CP_COMMIT();
    issue(1); CP_COMMIT();

    for (int kt = 0; kt < 8; kt++) {
        if (kt == 7) { CP_WAIT0(); } else { CP_WAIT1(); }
        __syncthreads();
        if (kt + 2 < 8) { issue(kt + 2); CP_COMMIT(); }

        const uint32_t stg = sb + (uint32_t)(kt % 3) * ASTAGE;

        #pragma unroll
        for (int sub = 0; sub < 2; sub++) {
            const uint32_t sKh = stg + (uint32_t)sub * 8192;
            const uint32_t sVh = stg + KTILE2 + (uint32_t)sub * 8192;

            // ---- S = Q K^T ----
            float s[8][4];
            #pragma unroll
            for (int j = 0; j < 8; j++)
                #pragma unroll
                for (int q = 0; q < 4; q++) s[j][q] = 0.f;

            #pragma unroll
            for (int ks = 0; ks < 4; ks++) {
                const uint32_t kx = (uint32_t)(ks << 5);
                uint32_t kh[4][4];
                #pragma unroll
                for (int p = 0; p < 4; p++)
                    LDSM4(kh[p], sKh + (offK[p] ^ kx));
                #pragma unroll
                for (int p = 0; p < 4; p++)
                    #pragma unroll
                    for (int h2 = 0; h2 < 2; h2++) {
                        int nt = 2*p + h2;
                        mma16816(s[nt], qh[ks], kh[p][2*h2], kh[p][2*h2+1]);
                    }
            }

            // ---- prefetch V fragments for ds=0 (hidden by exp work) ----
            uint32_t vh[4][4];
            #pragma unroll
            for (int dj = 0; dj < 4; dj++)
                LDSM4T(vh[dj], sVh + (offV[0] ^ (uint32_t)(dj << 5)));

            // ---- fixed-shift softmax: p = 2^(s - 13), accumulate li ----
            #pragma unroll
            for (int nt = 0; nt < 8; nt++) {
                u64 e0 = exp2s13x2(pk2(s[nt][0], s[nt][1]), EC);
                u64 e1 = exp2s13x2(pk2(s[nt][2], s[nt][3]), EC);
                upk2(e0, s[nt][0], s[nt][1]);
                upk2(e1, s[nt][2], s[nt][3]);
                ADD2(ls0, ls0, e0);
                ADD2(ls1, ls1, e1);
            }

            // ---- O += P V (V fragments pipelined) ----
            #pragma unroll
            for (int ds = 0; ds < 4; ds++) {
                uint32_t ph[4];
                #pragma unroll
                for (int half = 0; half < 2; half++) {
                    int nt = 2*ds + half;
                    ph[2*half]   = packhf(s[nt][0], s[nt][1]);
                    ph[2*half+1] = packhf(s[nt][2], s[nt][3]);
                }
                uint32_t vhn[4][4];
                if (ds < 3) {
                    #pragma unroll
                    for (int dj = 0; dj < 4; dj++)
                        LDSM4T(vhn[dj], sVh + (offV[ds+1] ^ (uint32_t)(dj << 5)));
                }
                #pragma unroll
                for (int dj = 0; dj < 4; dj++)
                    #pragma unroll
                    for (int h2 = 0; h2 < 2; h2++) {
                        int dt = 2*dj + h2;
                        mma16816(o[dt], ph, vh[dj][2*h2], vh[dj][2*h2+1]);
                    }
                if (ds < 3) {
                    #pragma unroll
                    for (int dj = 0; dj < 4; dj++)
                        #pragma unroll
                        for (int q = 0; q < 4; q++)
                            vh[dj][q] = vhn[dj][q];
                }
            }
        }
    }

    // ---- reduce li once, normalize, round fp16, store [B,N,C] ----
    float la, lb2, li0, li1;
    upk2(ls0, la, lb2); li0 = la + lb2;
    upk2(ls1, la, lb2); li1 = la + lb2;
    li0 += __shfl_xor_sync(~0u, li0, 1);
    li0 += __shfl_xor_sync(~0u, li0, 2);
    li1 += __shfl_xor_sync(~0u, li1, 1);
    li1 += __shfl_xor_sync(~0u, li1, 2);
    const float inv1 = 1.0f / li0;
    const float inv2 = 1.0f / li1;
    const int row1 = q0 + wid*16 + (lane >> 2);
    #pragma unroll
    for (int dt = 0; dt < 8; dt++) {
        int col = h*D_ + dt*8 + 2*(lane & 3);
        size_t i1 = (size_t)(b*N_ + row1) * C_ + col;
        size_t i2 = (size_t)(b*N_ + row1 + 8) * C_ + col;
        *(uint32_t*)(Oh + i1) = packhf(o[dt][0]*inv1, o[dt][1]*inv1);
        *(uint32_t*)(Oh + i2) = packhf(o[dt][2]*inv2, o[dt][3]*inv2);
    }
}

// ================= launch =================
extern "C" void kernel_launch(void* const* d_in, const int* in_sizes, int n_in,
                              void* d_out, int out_size)
{
    const float* x      = (const float*)d_in[0];
    const float* cosr   = (const float*)d_in[1];
    const float* sinr   = (const float*)d_in[2];
    const float* w_qkv  = (const float*)d_in[3];
    const float* q_ln_w = (const float*)d_in[4];
    const float* q_ln_b = (const float*)d_in[5];
    const float* k_ln_w = (const float*)d_in[6];
    const float* k_ln_b = (const float*)d_in[7];
    const float* w_proj = (const float*)d_in[8];
    const float* b_proj = (const float*)d_in[9];
    const int*   pP     = (const int*)d_in[10];
    const int*   pL     = (const int*)d_in[11];
    float* out = (float*)d_out;

    __half *xh, *wqh, *wph, *qh, *kh, *vh, *oh;
    cudaGetSymbolAddress((void**)&xh,  g_xh);
    cudaGetSymbolAddress((void**)&wqh, g_wqh);
    cudaGetSymbolAddress((void**)&wph, g_wph);
    cudaGetSymbolAddress((void**)&qh,  g_qh);
    cudaGetSymbolAddress((void**)&kh,  g_kh);
    cudaGetSymbolAddress((void**)&vh,  g_vh);
    cudaGetSymbolAddress((void**)&oh,  g_oh);

    cudaFuncSetAttribute(gemm_mma<false>, cudaFuncAttributeMaxDynamicSharedMemorySize, GEMM_SMEM);
    cudaFuncSetAttribute(gemm_mma<true>,  cudaFuncAttributeMaxDynamicSharedMemorySize, GEMM_SMEM);
    cudaFuncSetAttribute(attn_mma, cudaFuncAttributeMaxDynamicSharedMemorySize, ATT_SMEM);

    // 0) fused prep: x round + both weight transposes
    prep_all<<<XBLK + 1728 + 576, 256>>>((const float4*)x, xh,
                                         w_qkv, wqh, w_proj, wph);

    // 1) QKV projection with fused LN+RoPE epilogue -> fp16 Q/K/V
    gemm_mma<true><<<dim3(QKV_/256, M_/128), 512, GEMM_SMEM>>>(
        xh, wqh, nullptr, M_, QKV_, C_, nullptr,
        cosr, sinr, q_ln_w, q_ln_b, k_ln_w, k_ln_b, pP, pL,
        qh, kh, vh);

    // 2) attention -> fp16 [B,N,C]
    attn_mma<<<dim3(N_/128, H_, B_), 256, ATT_SMEM>>>(qh, kh, vh, oh);

    // 3) output projection + bias
    gemm_mma<false><<<dim3(C_/256, M_/128), 512, GEMM_SMEM>>>(
        oh, wph, out, M_, C_, C_, b_proj,
        nullptr, nullptr, nullptr, nullptr, nullptr, nullptr, nullptr, nullptr,
        nullptr, nullptr, nullptr);
}

// round 16
// speedup vs baseline: 1.0472x; 1.0472x over previous
#include <cuda_runtime.h>
#include <cuda_fp16.h>
#include <cstdint>

// Problem constants (fixed by setup_inputs)
#define B_   16
#define N_   1024
#define C_   768
#define H_   12
#define D_   64
#define M_   (B_*N_)     // 16384
#define QKV_ (3*C_)      // 2304

// ---------------- scratch (device globals: allocation-free) ----------------
__device__ __align__(16) __half g_xh[M_*C_];
__device__ __align__(16) __half g_wqh[QKV_*C_];        // [N,K] rounded
__device__ __align__(16) __half g_wph[C_*C_];          // [N,K] rounded
__device__ __align__(16) __half g_qh[B_*H_*N_*D_];
__device__ __align__(16) __half g_kh[B_*H_*N_*D_];
__device__ __align__(16) __half g_vh[B_*H_*N_*D_];
__device__ __align__(16) __half g_oh[M_*C_];

// ================= low-level helpers =================
__device__ __forceinline__ uint32_t smem_u32(const void* p) {
    uint32_t a;
    asm("{ .reg .u64 t; cvta.to.shared.u64 t, %1; cvt.u32.u64 %0, t; }"
        : "=r"(a) : "l"(p));
    return a;
}
__device__ __forceinline__ uint32_t sw128(uint32_t off) {
    return off ^ ((off >> 3) & 0x70);
}
__device__ __forceinline__ uint32_t swbase(uint32_t R) {
    return R ^ ((R >> 3) & 0x70);
}
#define CP_A16(s, g) \
    asm volatile("cp.async.cg.shared.global [%0], [%1], 16;" :: "r"(s), "l"(g) : "memory")
#define CP_COMMIT() asm volatile("cp.async.commit_group;" ::: "memory")
#define CP_WAIT1()  asm volatile("cp.async.wait_group 1;" ::: "memory")
#define CP_WAIT0()  asm volatile("cp.async.wait_group 0;" ::: "memory")

#define LDSM4(r, addr) \
    asm volatile("ldmatrix.sync.aligned.m8n8.x4.shared.b16 {%0,%1,%2,%3}, [%4];" \
        : "=r"((r)[0]), "=r"((r)[1]), "=r"((r)[2]), "=r"((r)[3]) : "r"(addr))
#define LDSM4T(r, addr) \
    asm volatile("ldmatrix.sync.aligned.m8n8.x4.trans.shared.b16 {%0,%1,%2,%3}, [%4];" \
        : "=r"((r)[0]), "=r"((r)[1]), "=r"((r)[2]), "=r"((r)[3]) : "r"(addr))

__device__ __forceinline__ void mma16816(float* c, const uint32_t* a,
                                         uint32_t b0, uint32_t b1) {
    asm volatile(
        "mma.sync.aligned.m16n8k16.row.col.f32.f16.f16.f32 "
        "{%0,%1,%2,%3}, {%4,%5,%6,%7}, {%8,%9}, {%0,%1,%2,%3};"
        : "+f"(c[0]), "+f"(c[1]), "+f"(c[2]), "+f"(c[3])
        : "r"(a[0]), "r"(a[1]), "r"(a[2]), "r"(a[3]), "r"(b0), "r"(b1));
}
__device__ __forceinline__ uint32_t packhf(float a, float b) {
    __half2 h = __floats2half2_rn(a, b);
    return *reinterpret_cast<uint32_t*>(&h);
}

// ---------- packed f32x2 helpers (sm_100+ base ISA) ----------
typedef unsigned long long u64;
__device__ __forceinline__ u64 pk2(float a, float b) {
    u64 r;
    asm("mov.b64 %0, {%1,%2};" : "=l"(r) : "f"(a), "f"(b));
    return r;
}
__device__ __forceinline__ void upk2(u64 p, float& a, float& b) {
    asm("mov.b64 {%0,%1}, %2;" : "=f"(a), "=f"(b) : "l"(p));
}
#define ADD2(d, a, b) asm("add.rn.f32x2 %0, %1, %2;" : "=l"(d) : "l"(a), "l"(b))
#define MUL2(d, a, b) asm("mul.rn.f32x2 %0, %1, %2;" : "=l"(d) : "l"(a), "l"(b))
#define FMA2(d, a, b, c) \
    asm("fma.rn.f32x2 %0, %1, %2, %3;" : "=l"(d) : "l"(a), "l"(b), "l"(c))

// packed exp2 with built-in shift: returns 2^(x - 13) for x in [-12, 12].
// Shift 13 >= Cauchy-Schwarz bound 11.54 folds into the exponent bias (ALU),
// costing zero fma-pipe ops. Degree-4 poly, rel err ~4e-5.
struct ExpC {
    u64 M, NM, C4, C3, C2, C1, C0;
    __device__ __forceinline__ void init() {
        M  = pk2(12582912.0f, 12582912.0f);
        NM = pk2(-12582912.0f, -12582912.0f);
        C4 = pk2(9.6181291e-3f, 9.6181291e-3f);
        C3 = pk2(5.5504109e-2f, 5.5504109e-2f);
        C2 = pk2(2.4022651e-1f, 2.4022651e-1f);
        C1 = pk2(6.9314718e-1f, 6.9314718e-1f);
        C0 = pk2(1.0f, 1.0f);
    }
};
__device__ __forceinline__ u64 exp2s13x2(u64 x, const ExpC& C) {
    u64 z, t, f, p, sc;
    ADD2(z, x, C.M);
    ADD2(t, z, C.NM);
    t ^= 0x8000000080000000ull;
    ADD2(f, x, t);
    p = C.C4;
    FMA2(p, p, f, C.C3);
    FMA2(p, p, f, C.C2);
    FMA2(p, p, f, C.C1);
    FMA2(p, p, f, C.C0);
    uint32_t elo = (uint32_t)z, ehi = (uint32_t)(z >> 32);
    uint32_t slo = (elo << 23) + 0x39000000u;   // bias - (13<<23)
    uint32_t shi = (ehi << 23) + 0x39000000u;
    asm("mov.b64 %0, {%1,%2};" : "=l"(sc) : "r"(slo), "r"(shi));
    MUL2(p, p, sc);
    return p;
}

// ================= fused prep kernel =================
#define XBLK (M_*C_/4/256)       // 12288

__global__ __launch_bounds__(256)
void prep_all(const float4* __restrict__ x, __half* __restrict__ xh,
              const float* __restrict__ wq, __half* __restrict__ wqh,
              const float* __restrict__ wp, __half* __restrict__ wph)
{
    __shared__ float t[32][33];
    const int bx = blockIdx.x;
    if (bx < XBLK) {
        const uint32_t i = bx * 256 + threadIdx.x;
        float4 v = x[i];
        *(__half2*)(xh + 4*(size_t)i)     = __floats2half2_rn(v.x, v.y);
        *(__half2*)(xh + 4*(size_t)i + 2) = __floats2half2_rn(v.z, v.w);
        return;
    }
    const float* W;
    __half* Th;
    int idx, Ndim;
    if (bx < XBLK + 1728) {
        idx = bx - XBLK; W = wq; Th = wqh; Ndim = QKV_;
    } else {
        idx = bx - XBLK - 1728; W = wp; Th = wph; Ndim = C_;
    }
    const int kk = (idx % 24) * 32, nn = (idx / 24) * 32;
    const int tx = threadIdx.x & 31, ty = threadIdx.x >> 5;
    #pragma unroll
    for (int i = ty; i < 32; i += 8)
        t[i][tx] = W[(size_t)(kk + i) * Ndim + nn + tx];
    __syncthreads();
    #pragma unroll
    for (int i = ty; i < 32; i += 8)
        Th[(size_t)(nn + i) * C_ + kk + tx] = __float2half_rn(t[tx][i]);
}

// ================= fp16 HMMA GEMM (R14 config: 128x128, 256 thr, 2 CTA/SM) =
#define GTILE 16384                 // 128 rows x 128 bytes
#define GSTAGE (2*GTILE)            // A,B = 32 KB
#define GEMM_SMEM (3*GSTAGE)        // 98304

template<bool FUSED>
__global__ __launch_bounds__(256, 2)
void gemm_mma(const __half* __restrict__ Ah, const __half* __restrict__ Bh,
              float* __restrict__ Cm, int Mdim, int Ndim, int Kdim,
              const float* __restrict__ bias,
              const float* __restrict__ cosr, const float* __restrict__ sinr,
              const float* __restrict__ qw, const float* __restrict__ qb,
              const float* __restrict__ kw, const float* __restrict__ kb,
              const int* __restrict__ pP, const int* __restrict__ pL,
              __half* __restrict__ Qh,
              __half* __restrict__ Kh, __half* __restrict__ Vh)
{
    extern __shared__ char smem[];
    const uint32_t sb = smem_u32(smem);
    const int tid = threadIdx.x;
    const int wid = tid >> 5, lane = tid & 31;
    const int m0 = blockIdx.y * 128, n0 = blockIdx.x * 128;
    const int wm = (wid & 3) * 32, wn = (wid >> 2) * 64;
    const int nchunks = Kdim / 64;   // 12

    const int r0 = tid >> 3, u8 = tid & 7;
    const __half* pA = Ah + (size_t)(m0 + r0) * Kdim + u8 * 8;
    const __half* pB = Bh + (size_t)(n0 + r0) * Kdim + u8 * 8;
    const uint32_t d0 = sw128((uint32_t)(r0 * 128 + u8 * 16));
    const size_t rstr = (size_t)32 * Kdim;

    auto issue = [&](int c) {
        const uint32_t stg = sb + (uint32_t)(c % 3) * GSTAGE;
        const int k0 = c * 64;
        const __half* a = pA + k0;
        const __half* b = pB + k0;
        #pragma unroll
        for (int t = 0; t < 4; t++) {
            CP_A16(stg + d0 + t*4096,
                   (u64)__cvta_generic_to_global(a + t*rstr));
            CP_A16(stg + GTILE + d0 + t*4096,
                   (u64)__cvta_generic_to_global(b + t*rstr));
        }
    };

    uint32_t offA[2], offB[4];
    #pragma unroll
    for (int mt = 0; mt < 2; mt++)
        offA[mt] = swbase((uint32_t)((wm + mt*16 + (lane & 15)) * 128)) ^ (lane & 16);
    #pragma unroll
    for (int p = 0; p < 4; p++)
        offB[p] = swbase((uint32_t)((wn + p*16 + (lane & 7) + ((lane & 16) >> 1)) * 128))
                  ^ ((lane & 8) << 1);

    float acc[2][8][4];
    #pragma unroll
    for (int i = 0; i < 2; i++)
        #pragma unroll
        for (int j = 0; j < 8; j++)
            #pragma unroll
            for (int q = 0; q < 4; q++) acc[i][j][q] = 0.f;

    issue(0); CP_COMMIT();
    issue(1); CP_COMMIT();

    for (int c = 0; c < nchunks; c++) {
        if (c == nchunks - 1) { CP_WAIT0(); } else { CP_WAIT1(); }
        __syncthreads();
        if (c + 2 < nchunks) { issue(c + 2); CP_COMMIT(); }

        const uint32_t sAh = sb + (uint32_t)(c % 3) * GSTAGE;
        const uint32_t sBh = sAh + GTILE;

        #pragma unroll
        for (int ks = 0; ks < 4; ks++) {
            const uint32_t kx = (uint32_t)(ks << 5);
            uint32_t ah[2][4];
            #pragma unroll
            for (int mt = 0; mt < 2; mt++)
                LDSM4(ah[mt], sAh + (offA[mt] ^ kx));
            uint32_t bh[4][4];
            #pragma unroll
            for (int p = 0; p < 4; p++)
                LDSM4(bh[p], sBh + (offB[p] ^ kx));
            #pragma unroll
            for (int mt = 0; mt < 2; mt++)
                #pragma unroll
                for (int p = 0; p < 4; p++)
                    #pragma unroll
                    for (int h2 = 0; h2 < 2; h2++) {
                        int nt = 2*p + h2;
                        mma16816(acc[mt][nt], ah[mt], bh[p][2*h2], bh[p][2*h2+1]);
                    }
        }
    }

    if (!FUSED) {
        #pragma unroll
        for (int mt = 0; mt < 2; mt++)
            #pragma unroll
            for (int nt = 0; nt < 8; nt++) {
                int row = m0 + wm + mt*16 + (lane >> 2);
                int col = n0 + wn + nt*8 + 2*(lane & 3);
                float b0 = 0.f, b1 = 0.f;
                if (bias) { b0 = bias[col]; b1 = bias[col + 1]; }
                float2 v0 = make_float2(acc[mt][nt][0] + b0, acc[mt][nt][1] + b1);
                float2 v1 = make_float2(acc[mt][nt][2] + b0, acc[mt][nt][3] + b1);
                *(float2*)(Cm + (size_t)row * Ndim + col)       = v0;
                *(float2*)(Cm + (size_t)(row + 8) * Ndim + col) = v1;
            }
    } else {
        const int gcol = n0 + wn;
        const int kind = gcol / C_;             // 0=q, 1=k, 2=v
        const int head = (gcol % C_) / D_;
        const int Pp = __ldg(pP), Ll = __ldg(pL);
        const float* lw = (kind == 0) ? qw : kw;
        const float* lb = (kind == 0) ? qb : kb;
        const float QSC = 0.18033688011112042f; // (1/8)*log2(e)

        #pragma unroll
        for (int mt = 0; mt < 2; mt++) {
            const int m1 = m0 + wm + mt*16 + (lane >> 2);
            const int m2 = m1 + 8;
            const int b1i = m1 >> 10, n1 = m1 & (N_-1);
            const int b2i = m2 >> 10, n2 = m2 & (N_-1);
            const size_t o1 = (((size_t)(b1i*H_ + head))*N_ + n1) * D_;
            const size_t o2 = (((size_t)(b2i*H_ + head))*N_ + n2) * D_;

            if (kind == 2) {
                #pragma unroll
                for (int nt = 0; nt < 8; nt++) {
                    int col = nt*8 + 2*(lane & 3);
                    *(uint32_t*)(Vh + o1 + col) = packhf(acc[mt][nt][0], acc[mt][nt][1]);
                    *(uint32_t*)(Vh + o2 + col) = packhf(acc[mt][nt][2], acc[mt][nt][3]);
                }
            } else {
                float s1 = 0.f, s2 = 0.f;
                #pragma unroll
                for (int nt = 0; nt < 8; nt++) {
                    s1 += acc[mt][nt][0] + acc[mt][nt][1];
                    s2 += acc[mt][nt][2] + acc[mt][nt][3];
                }
                s1 += __shfl_xor_sync(~0u, s1, 1); s1 += __shfl_xor_sync(~0u, s1, 2);
                s2 += __shfl_xor_sync(~0u, s2, 1); s2 += __shfl_xor_sync(~0u, s2, 2);
                const float mu1 = s1 * (1.0f/64.0f), mu2 = s2 * (1.0f/64.0f);
                float v1 = 0.f, v2 = 0.f;
                #pragma unroll
                for (int nt = 0; nt < 8; nt++) {
                    float d0f = acc[mt][nt][0] - mu1, d1f = acc[mt][nt][1] - mu1;
                    float d2f = acc[mt][nt][2] - mu2, d3f = acc[mt][nt][3] - mu2;
                    v1 += d0f*d0f + d1f*d1f;
                    v2 += d2f*d2f + d3f*d3f;
                }
                v1 += __shfl_xor_sync(~0u, v1, 1); v1 += __shfl_xor_sync(~0u, v1, 2);
                v2 += __shfl_xor_sync(~0u, v2, 1); v2 += __shfl_xor_sync(~0u, v2, 2);
                const float iv1 = rsqrtf(v1*(1.0f/64.0f) + 1e-5f);
                const float iv2 = rsqrtf(v2*(1.0f/64.0f) + 1e-5f);
                const bool r1 = (n1 >= Pp) && (n1 < N_ - Ll);
                const bool r2 = (n2 >= Pp) && (n2 < N_ - Ll);

                #pragma unroll
                for (int nt = 0; nt < 8; nt++) {
                    const int col  = nt*8 + 2*(lane & 3);
                    const int colp = nt*4 + (lane & 3);
                    float2 w2 = *(const float2*)(lw + col);
                    float2 bb = *(const float2*)(lb + col);
                    float y0 = fmaf((acc[mt][nt][0]-mu1)*iv1, w2.x, bb.x);
                    float y1 = fmaf((acc[mt][nt][1]-mu1)*iv1, w2.y, bb.y);
                    float y2 = fmaf((acc[mt][nt][2]-mu2)*iv2, w2.x, bb.x);
                    float y3 = fmaf((acc[mt][nt][3]-mu2)*iv2, w2.y, bb.y);
                    if (r1) {
                        float rc = cosr[(n1-Pp)*32 + colp], rs = sinr[(n1-Pp)*32 + colp];
                        float t0 = y0*rc - y1*rs, t1 = y0*rs + y1*rc;
                        y0 = t0; y1 = t1;
                    }
                    if (r2) {
                        float rc = cosr[(n2-Pp)*32 + colp], rs = sinr[(n2-Pp)*32 + colp];
                        float t2 = y2*rc - y3*rs, t3 = y2*rs + y3*rc;
                        y2 = t2; y3 = t3;
                    }
                    if (kind == 0) {
                        y0 *= QSC; y1 *= QSC; y2 *= QSC; y3 *= QSC;
                        *(uint32_t*)(Qh + o1 + col) = packhf(y0, y1);
                        *(uint32_t*)(Qh + o2 + col) = packhf(y2, y3);
                    } else {
                        *(uint32_t*)(Kh + o1 + col) = packhf(y0, y1);
                        *(uint32_t*)(Kh + o2 + col) = packhf(y2, y3);
                    }
                }
            }
        }
    }
}

// ================= HMMA flash attention (fixed-shift softmax) =============
// |S_log2| <= 11.54 (Cauchy-Schwarz after LN); p = 2^(s-13) via exp2s13x2.
#define KTILE2 16384                  // 128 rows x 128 bytes
#define ASTAGE (2*KTILE2)             // Kh,Vh = 32 KB
#define ATT_SMEM (3*ASTAGE)           // 98304

__global__ __launch_bounds__(256, 2)
void attn_mma(const __half* __restrict__ Qh,
              const __half* __restrict__ Kh, const __half* __restrict__ Vh,
              __half* __restrict__ Oh)
{
    extern __shared__ char smem[];
    const uint32_t sb = smem_u32(smem);
    const int tid = threadIdx.x;
    const int wid = tid >> 5, lane = tid & 31;
    const int b = blockIdx.z, h = blockIdx.y;
    const int q0 = blockIdx.x * 128;
    const size_t base = ((size_t)(b*H_ + h)) * N_;

    ExpC EC; EC.init();

    const int r0 = tid >> 3, u8 = tid & 7;
    const uint32_t d0 = sw128((uint32_t)(r0 * 128 + u8 * 16));
    const __half* pK = Kh + (base + r0) * D_ + u8 * 8;
    const __half* pV = Vh + (base + r0) * D_ + u8 * 8;

    // ---- stage Q tile (16 KB, in stage-0 area) ----
    {
        const __half* pQ = Qh + (base + q0 + r0) * D_ + u8 * 8;
        #pragma unroll
        for (int t = 0; t < 4; t++) {
            uint4 v = *(const uint4*)(pQ + t * 32 * D_);
            *(uint4*)(smem + d0 + t*4096) = v;
        }
    }
    __syncthreads();

    uint32_t qh[4][4];
    {
        const uint32_t offQ = swbase((uint32_t)((wid*16 + (lane & 15)) * 128)) ^ (lane & 16);
        #pragma unroll
        for (int ks = 0; ks < 4; ks++)
            LDSM4(qh[ks], sb + (offQ ^ (uint32_t)(ks << 5)));
    }
    __syncthreads();   // Q reads done; smem reusable for KV stages

    uint32_t offK[4], offV[4];
    #pragma unroll
    for (int p = 0; p < 4; p++)
        offK[p] = swbase((uint32_t)((p*16 + (lane & 7) + ((lane & 16) >> 1)) * 128))
                  ^ ((lane & 8) << 1);
    #pragma unroll
    for (int ds = 0; ds < 4; ds++)
        offV[ds] = swbase((uint32_t)((ds*16 + (lane & 15)) * 128)) ^ (lane & 16);

    auto issue = [&](int kt) {
        const uint32_t stg = sb + (uint32_t)(kt % 3) * ASTAGE;
        const int koff = kt * 128 * D_;
        const __half* k = pK + koff;
        const __half* v = pV + koff;
        #pragma unroll
        for (int t = 0; t < 4; t++) {
            CP_A16(stg + d0 + t*4096,
                   (u64)__cvta_generic_to_global(k + t * 32 * D_));
            CP_A16(stg + KTILE2 + d0 + t*4096,
                   (u64)__cvta_generic_to_global(v + t * 32 * D_));
        }
    };

    float o[8][4];
    #pragma unroll
    for (int j = 0; j < 8; j++)
        #pragma unroll
        for (int q = 0; q < 4; q++) o[j][q] = 0.f;
    u64 ls0 = 0ull, ls1 = 0ull;            // packed li accumulators

    issue(0); CP_COMMIT();
    issue(1); CP_COMMIT();

    for (int kt = 0; kt < 8; kt++) {
        if (kt == 7) { CP_WAIT0(); } else { CP_WAIT1(); }
        __syncthreads();
        if (kt + 2 < 8) { issue(kt + 2); CP_COMMIT(); }

        const uint32_t stg = sb + (uint32_t)(kt % 3) * ASTAGE;

        #pragma unroll
        for (int sub = 0; sub < 2; sub++) {
            const uint32_t sKh = stg + (uint32_t)sub * 8192;
            const uint32_t sVh = stg + KTILE2 + (uint32_t)sub * 8192;

            // ---- S = Q K^T ----
            float s[8][4];
            #pragma unroll
            for (int j = 0; j < 8; j++)
                #pragma unroll
                for (int q = 0; q < 4; q++) s[j][q] = 0.f;

            #pragma unroll
            for (int ks = 0; ks < 4; ks++) {
                const uint32_t kx = (uint32_t)(ks << 5);
                uint32_t kh[4][4];
                #pragma unroll
                for (int p = 0; p < 4; p++)
                    LDSM4(kh[p], sKh + (offK[p] ^ kx));
                #pragma unroll
                for (int p = 0; p < 4; p++)
                    #pragma unroll
                    for (int h2 = 0; h2 < 2; h2++) {
                        int nt = 2*p + h2;
                        mma16816(s[nt], qh[ks], kh[p][2*h2], kh[p][2*h2+1]);
                    }
            }

            // ---- prefetch V fragments for ds=0 (hidden by exp work) ----
            uint32_t vh[4][4];
            #pragma unroll
            for (int dj = 0; dj < 4; dj++)
                LDSM4T(vh[dj], sVh + (offV[0] ^ (uint32_t)(dj << 5)));

            // ---- fixed-shift softmax: p = 2^(s - 13), accumulate li ----
            #pragma unroll
            for (int nt = 0; nt < 8; nt++) {
                u64 e0 = exp2s13x2(pk2(s[nt][0], s[nt][1]), EC);
                u64 e1 = exp2s13x2(pk2(s[nt][2], s[nt][3]), EC);
                upk2(e0, s[nt][0], s[nt][1]);
                upk2(e1, s[nt][2], s[nt][3]);
                ADD2(ls0, ls0, e0);
                ADD2(ls1, ls1, e1);
            }

            // ---- O += P V (V fragments pipelined) ----
            #pragma unroll
            for (int ds = 0; ds < 4; ds++) {
                uint32_t ph[4];
                #pragma unroll
                for (int half = 0; half < 2; half++) {
                    int nt = 2*ds + half;
                    ph[2*half]   = packhf(s[nt][0], s[nt][1]);
                    ph[2*half+1] = packhf(s[nt][2], s[nt][3]);
                }
                uint32_t vhn[4][4];
                if (ds < 3) {
                    #pragma unroll
                    for (int dj = 0; dj < 4; dj++)
                        LDSM4T(vhn[dj], sVh + (offV[ds+1] ^ (uint32_t)(dj << 5)));
                }
                #pragma unroll
                for (int dj = 0; dj < 4; dj++)
                    #pragma unroll
                    for (int h2 = 0; h2 < 2; h2++) {
                        int dt = 2*dj + h2;
                        mma16816(o[dt], ph, vh[dj][2*h2], vh[dj][2*h2+1]);
                    }
                if (ds < 3) {
                    #pragma unroll
                    for (int dj = 0; dj < 4; dj++)
                        #pragma unroll
                        for (int q = 0; q < 4; q++)
                            vh[dj][q] = vhn[dj][q];
                }
            }
        }
    }

    // ---- reduce li once, normalize, round fp16, store [B,N,C] ----
    float la, lb2, li0, li1;
    upk2(ls0, la, lb2); li0 = la + lb2;
    upk2(ls1, la, lb2); li1 = la + lb2;
    li0 += __shfl_xor_sync(~0u, li0, 1);
    li0 += __shfl_xor_sync(~0u, li0, 2);
    li1 += __shfl_xor_sync(~0u, li1, 1);
    li1 += __shfl_xor_sync(~0u, li1, 2);
    const float inv1 = 1.0f / li0;
    const float inv2 = 1.0f / li1;
    const int row1 = q0 + wid*16 + (lane >> 2);
    #pragma unroll
    for (int dt = 0; dt < 8; dt++) {
        int col = h*D_ + dt*8 + 2*(lane & 3);
        size_t i1 = (size_t)(b*N_ + row1) * C_ + col;
        size_t i2 = (size_t)(b*N_ + row1 + 8) * C_ + col;
        *(uint32_t*)(Oh + i1) = packhf(o[dt][0]*inv1, o[dt][1]*inv1);
        *(uint32_t*)(Oh + i2) = packhf(o[dt][2]*inv2, o[dt][3]*inv2);
    }
}

// ================= launch =================
extern "C" void kernel_launch(void* const* d_in, const int* in_sizes, int n_in,
                              void* d_out, int out_size)
{
    const float* x      = (const float*)d_in[0];
    const float* cosr   = (const float*)d_in[1];
    const float* sinr   = (const float*)d_in[2];
    const float* w_qkv  = (const float*)d_in[3];
    const float* q_ln_w = (const float*)d_in[4];
    const float* q_ln_b = (const float*)d_in[5];
    const float* k_ln_w = (const float*)d_in[6];
    const float* k_ln_b = (const float*)d_in[7];
    const float* w_proj = (const float*)d_in[8];
    const float* b_proj = (const float*)d_in[9];
    const int*   pP     = (const int*)d_in[10];
    const int*   pL     = (const int*)d_in[11];
    float* out = (float*)d_out;

    __half *xh, *wqh, *wph, *qh, *kh, *vh, *oh;
    cudaGetSymbolAddress((void**)&xh,  g_xh);
    cudaGetSymbolAddress((void**)&wqh, g_wqh);
    cudaGetSymbolAddress((void**)&wph, g_wph);
    cudaGetSymbolAddress((void**)&qh,  g_qh);
    cudaGetSymbolAddress((void**)&kh,  g_kh);
    cudaGetSymbolAddress((void**)&vh,  g_vh);
    cudaGetSymbolAddress((void**)&oh,  g_oh);

    cudaFuncSetAttribute(gemm_mma<false>, cudaFuncAttributeMaxDynamicSharedMemorySize, GEMM_SMEM);
    cudaFuncSetAttribute(gemm_mma<true>,  cudaFuncAttributeMaxDynamicSharedMemorySize, GEMM_SMEM);
    cudaFuncSetAttribute(attn_mma, cudaFuncAttributeMaxDynamicSharedMemorySize, ATT_SMEM);

    // 0) fused prep: x round + both weight transposes
    prep_all<<<XBLK + 1728 + 576, 256>>>((const float4*)x, xh,
                                         w_qkv, wqh, w_proj, wph);

    // 1) QKV projection with fused LN+RoPE epilogue -> fp16 Q/K/V
    gemm_mma<true><<<dim3(QKV_/128, M_/128), 256, GEMM_SMEM>>>(
        xh, wqh, nullptr, M_, QKV_, C_, nullptr,
        cosr, sinr, q_ln_w, q_ln_b, k_ln_w, k_ln_b, pP, pL,
        qh, kh, vh);

    // 2) attention -> fp16 [B,N,C]
    attn_mma<<<dim3(N_/128, H_, B_), 256, ATT_SMEM>>>(qh, kh, vh, oh);

    // 3) output projection + bias
    gemm_mma<false><<<dim3(C_/128, M_/128), 256, GEMM_SMEM>>>(
        oh, wph, out, M_, C_, C_, b_proj,
        nullptr, nullptr, nullptr, nullptr, nullptr, nullptr, nullptr, nullptr,
        nullptr, nullptr, nullptr);
}

// round 17
// speedup vs baseline: 1.0522x; 1.0048x over previous
#include <cuda_runtime.h>
#include <cuda_fp16.h>
#include <cstdint>

// Problem constants (fixed by setup_inputs)
#define B_   16
#define N_   1024
#define C_   768
#define H_   12
#define D_   64
#define M_   (B_*N_)     // 16384
#define QKV_ (3*C_)      // 2304

// ---------------- scratch (device globals: allocation-free) ----------------
__device__ __align__(16) __half g_xh[M_*C_];
__device__ __align__(16) __half g_wqh[QKV_*C_];        // [N,K] rounded
__device__ __align__(16) __half g_wph[C_*C_];          // [N,K] rounded
__device__ __align__(16) __half g_qh[B_*H_*N_*D_];
__device__ __align__(16) __half g_kh[B_*H_*N_*D_];
__device__ __align__(16) __half g_vh[B_*H_*N_*D_];
__device__ __align__(16) __half g_oh[M_*C_];

// ================= low-level helpers =================
__device__ __forceinline__ uint32_t smem_u32(const void* p) {
    uint32_t a;
    asm("{ .reg .u64 t; cvta.to.shared.u64 t, %1; cvt.u32.u64 %0, t; }"
        : "=r"(a) : "l"(p));
    return a;
}
__device__ __forceinline__ uint32_t sw128(uint32_t off) {
    return off ^ ((off >> 3) & 0x70);
}
__device__ __forceinline__ uint32_t swbase(uint32_t R) {
    return R ^ ((R >> 3) & 0x70);
}
#define CP_A16(s, g) \
    asm volatile("cp.async.cg.shared.global [%0], [%1], 16;" :: "r"(s), "l"(g) : "memory")
#define CP_COMMIT() asm volatile("cp.async.commit_group;" ::: "memory")
#define CP_WAIT1()  asm volatile("cp.async.wait_group 1;" ::: "memory")
#define CP_WAIT0()  asm volatile("cp.async.wait_group 0;" ::: "memory")

#define LDSM4(r, addr) \
    asm volatile("ldmatrix.sync.aligned.m8n8.x4.shared.b16 {%0,%1,%2,%3}, [%4];" \
        : "=r"((r)[0]), "=r"((r)[1]), "=r"((r)[2]), "=r"((r)[3]) : "r"(addr))
#define LDSM4T(r, addr) \
    asm volatile("ldmatrix.sync.aligned.m8n8.x4.trans.shared.b16 {%0,%1,%2,%3}, [%4];" \
        : "=r"((r)[0]), "=r"((r)[1]), "=r"((r)[2]), "=r"((r)[3]) : "r"(addr))

__device__ __forceinline__ void mma16816(float* c, const uint32_t* a,
                                         uint32_t b0, uint32_t b1) {
    asm volatile(
        "mma.sync.aligned.m16n8k16.row.col.f32.f16.f16.f32 "
        "{%0,%1,%2,%3}, {%4,%5,%6,%7}, {%8,%9}, {%0,%1,%2,%3};"
        : "+f"(c[0]), "+f"(c[1]), "+f"(c[2]), "+f"(c[3])
        : "r"(a[0]), "r"(a[1]), "r"(a[2]), "r"(a[3]), "r"(b0), "r"(b1));
}
__device__ __forceinline__ uint32_t packhf(float a, float b) {
    __half2 h = __floats2half2_rn(a, b);
    return *reinterpret_cast<uint32_t*>(&h);
}

// ---------- packed f32x2 helpers (sm_100+ base ISA) ----------
typedef unsigned long long u64;
__device__ __forceinline__ u64 pk2(float a, float b) {
    u64 r;
    asm("mov.b64 %0, {%1,%2};" : "=l"(r) : "f"(a), "f"(b));
    return r;
}
__device__ __forceinline__ void upk2(u64 p, float& a, float& b) {
    asm("mov.b64 {%0,%1}, %2;" : "=f"(a), "=f"(b) : "l"(p));
}
#define ADD2(d, a, b) asm("add.rn.f32x2 %0, %1, %2;" : "=l"(d) : "l"(a), "l"(b))
#define MUL2(d, a, b) asm("mul.rn.f32x2 %0, %1, %2;" : "=l"(d) : "l"(a), "l"(b))
#define FMA2(d, a, b, c) \
    asm("fma.rn.f32x2 %0, %1, %2, %3;" : "=l"(d) : "l"(a), "l"(b), "l"(c))

// packed exp2 with built-in shift: returns 2^(x - 13) for x in [-12, 12].
// Shift 13 >= Cauchy-Schwarz bound 11.54 (LN rows have norm 8; q scaled by
// log2(e)/8). Softmax shift-invariance makes the constant shift exact.
struct ExpC {
    u64 M, NM, C4, C3, C2, C1, C0;
    __device__ __forceinline__ void init() {
        M  = pk2(12582912.0f, 12582912.0f);
        NM = pk2(-12582912.0f, -12582912.0f);
        C4 = pk2(9.6181291e-3f, 9.6181291e-3f);
        C3 = pk2(5.5504109e-2f, 5.5504109e-2f);
        C2 = pk2(2.4022651e-1f, 2.4022651e-1f);
        C1 = pk2(6.9314718e-1f, 6.9314718e-1f);
        C0 = pk2(1.0f, 1.0f);
    }
};
__device__ __forceinline__ u64 exp2s13x2(u64 x, const ExpC& C) {
    u64 z, t, f, p, sc;
    ADD2(z, x, C.M);
    ADD2(t, z, C.NM);
    t ^= 0x8000000080000000ull;
    ADD2(f, x, t);
    p = C.C4;
    FMA2(p, p, f, C.C3);
    FMA2(p, p, f, C.C2);
    FMA2(p, p, f, C.C1);
    FMA2(p, p, f, C.C0);
    uint32_t elo = (uint32_t)z, ehi = (uint32_t)(z >> 32);
    uint32_t slo = (elo << 23) + 0x39000000u;   // bias - (13<<23)
    uint32_t shi = (ehi << 23) + 0x39000000u;
    asm("mov.b64 %0, {%1,%2};" : "=l"(sc) : "r"(slo), "r"(shi));
    MUL2(p, p, sc);
    return p;
}

// ================= fused prep kernel =================
#define XBLK (M_*C_/4/256)       // 12288

__global__ __launch_bounds__(256)
void prep_all(const float4* __restrict__ x, __half* __restrict__ xh,
              const float* __restrict__ wq, __half* __restrict__ wqh,
              const float* __restrict__ wp, __half* __restrict__ wph)
{
    __shared__ float t[32][33];
    const int bx = blockIdx.x;
    if (bx < XBLK) {
        const uint32_t i = bx * 256 + threadIdx.x;
        float4 v = x[i];
        *(__half2*)(xh + 4*(size_t)i)     = __floats2half2_rn(v.x, v.y);
        *(__half2*)(xh + 4*(size_t)i + 2) = __floats2half2_rn(v.z, v.w);
        return;
    }
    const float* W;
    __half* Th;
    int idx, Ndim;
    if (bx < XBLK + 1728) {
        idx = bx - XBLK; W = wq; Th = wqh; Ndim = QKV_;
    } else {
        idx = bx - XBLK - 1728; W = wp; Th = wph; Ndim = C_;
    }
    const int kk = (idx % 24) * 32, nn = (idx / 24) * 32;
    const int tx = threadIdx.x & 31, ty = threadIdx.x >> 5;
    #pragma unroll
    for (int i = ty; i < 32; i += 8)
        t[i][tx] = W[(size_t)(kk + i) * Ndim + nn + tx];
    __syncthreads();
    #pragma unroll
    for (int i = ty; i < 32; i += 8)
        Th[(size_t)(nn + i) * C_ + kk + tx] = __float2half_rn(t[tx][i]);
}

// ================= fp16 HMMA GEMM (128x128, 256 thr, 2 CTA/SM) =============
#define GTILE 16384                 // 128 rows x 128 bytes
#define GSTAGE (2*GTILE)            // A,B = 32 KB
#define GEMM_SMEM (3*GSTAGE)        // 98304

template<bool FUSED>
__global__ __launch_bounds__(256, 2)
void gemm_mma(const __half* __restrict__ Ah, const __half* __restrict__ Bh,
              float* __restrict__ Cm, int Mdim, int Ndim, int Kdim,
              const float* __restrict__ bias,
              const float* __restrict__ cosr, const float* __restrict__ sinr,
              const float* __restrict__ qw, const float* __restrict__ qb,
              const float* __restrict__ kw, const float* __restrict__ kb,
              const int* __restrict__ pP, const int* __restrict__ pL,
              __half* __restrict__ Qh,
              __half* __restrict__ Kh, __half* __restrict__ Vh)
{
    extern __shared__ char smem[];
    const uint32_t sb = smem_u32(smem);
    const int tid = threadIdx.x;
    const int wid = tid >> 5, lane = tid & 31;
    const int m0 = blockIdx.y * 128, n0 = blockIdx.x * 128;
    const int wm = (wid & 3) * 32, wn = (wid >> 2) * 64;
    const int nchunks = Kdim / 64;   // 12

    const int r0 = tid >> 3, u8 = tid & 7;
    const __half* pA = Ah + (size_t)(m0 + r0) * Kdim + u8 * 8;
    const __half* pB = Bh + (size_t)(n0 + r0) * Kdim + u8 * 8;
    const uint32_t d0 = sw128((uint32_t)(r0 * 128 + u8 * 16));
    const size_t rstr = (size_t)32 * Kdim;

    auto issue = [&](int c) {
        const uint32_t stg = sb + (uint32_t)(c % 3) * GSTAGE;
        const int k0 = c * 64;
        const __half* a = pA + k0;
        const __half* b = pB + k0;
        #pragma unroll
        for (int t = 0; t < 4; t++) {
            CP_A16(stg + d0 + t*4096,
                   (u64)__cvta_generic_to_global(a + t*rstr));
            CP_A16(stg + GTILE + d0 + t*4096,
                   (u64)__cvta_generic_to_global(b + t*rstr));
        }
    };

    uint32_t offA[2], offB[4];
    #pragma unroll
    for (int mt = 0; mt < 2; mt++)
        offA[mt] = swbase((uint32_t)((wm + mt*16 + (lane & 15)) * 128)) ^ (lane & 16);
    #pragma unroll
    for (int p = 0; p < 4; p++)
        offB[p] = swbase((uint32_t)((wn + p*16 + (lane & 7) + ((lane & 16) >> 1)) * 128))
                  ^ ((lane & 8) << 1);

    float acc[2][8][4];
    #pragma unroll
    for (int i = 0; i < 2; i++)
        #pragma unroll
        for (int j = 0; j < 8; j++)
            #pragma unroll
            for (int q = 0; q < 4; q++) acc[i][j][q] = 0.f;

    issue(0); CP_COMMIT();
    issue(1); CP_COMMIT();

    for (int c = 0; c < nchunks; c++) {
        if (c == nchunks - 1) { CP_WAIT0(); } else { CP_WAIT1(); }
        __syncthreads();
        if (c + 2 < nchunks) { issue(c + 2); CP_COMMIT(); }

        const uint32_t sAh = sb + (uint32_t)(c % 3) * GSTAGE;
        const uint32_t sBh = sAh + GTILE;

        #pragma unroll
        for (int ks = 0; ks < 4; ks++) {
            const uint32_t kx = (uint32_t)(ks << 5);
            uint32_t ah[2][4];
            #pragma unroll
            for (int mt = 0; mt < 2; mt++)
                LDSM4(ah[mt], sAh + (offA[mt] ^ kx));
            uint32_t bh[4][4];
            #pragma unroll
            for (int p = 0; p < 4; p++)
                LDSM4(bh[p], sBh + (offB[p] ^ kx));
            #pragma unroll
            for (int mt = 0; mt < 2; mt++)
                #pragma unroll
                for (int p = 0; p < 4; p++)
                    #pragma unroll
                    for (int h2 = 0; h2 < 2; h2++) {
                        int nt = 2*p + h2;
                        mma16816(acc[mt][nt], ah[mt], bh[p][2*h2], bh[p][2*h2+1]);
                    }
        }
    }

    if (!FUSED) {
        #pragma unroll
        for (int mt = 0; mt < 2; mt++)
            #pragma unroll
            for (int nt = 0; nt < 8; nt++) {
                int row = m0 + wm + mt*16 + (lane >> 2);
                int col = n0 + wn + nt*8 + 2*(lane & 3);
                float b0 = 0.f, b1 = 0.f;
                if (bias) { b0 = bias[col]; b1 = bias[col + 1]; }
                float2 v0 = make_float2(acc[mt][nt][0] + b0, acc[mt][nt][1] + b1);
                float2 v1 = make_float2(acc[mt][nt][2] + b0, acc[mt][nt][3] + b1);
                *(float2*)(Cm + (size_t)row * Ndim + col)       = v0;
                *(float2*)(Cm + (size_t)(row + 8) * Ndim + col) = v1;
            }
    } else {
        const int gcol = n0 + wn;
        const int kind = gcol / C_;             // 0=q, 1=k, 2=v
        const int head = (gcol % C_) / D_;
        const int Pp = __ldg(pP), Ll = __ldg(pL);
        const float* lw = (kind == 0) ? qw : kw;
        const float* lb = (kind == 0) ? qb : kb;
        const float QSC = 0.18033688011112042f; // (1/8)*log2(e)

        #pragma unroll
        for (int mt = 0; mt < 2; mt++) {
            const int m1 = m0 + wm + mt*16 + (lane >> 2);
            const int m2 = m1 + 8;
            const int b1i = m1 >> 10, n1 = m1 & (N_-1);
            const int b2i = m2 >> 10, n2 = m2 & (N_-1);
            const size_t o1 = (((size_t)(b1i*H_ + head))*N_ + n1) * D_;
            const size_t o2 = (((size_t)(b2i*H_ + head))*N_ + n2) * D_;

            if (kind == 2) {
                #pragma unroll
                for (int nt = 0; nt < 8; nt++) {
                    int col = nt*8 + 2*(lane & 3);
                    *(uint32_t*)(Vh + o1 + col) = packhf(acc[mt][nt][0], acc[mt][nt][1]);
                    *(uint32_t*)(Vh + o2 + col) = packhf(acc[mt][nt][2], acc[mt][nt][3]);
                }
            } else {
                float s1 = 0.f, s2 = 0.f;
                #pragma unroll
                for (int nt = 0; nt < 8; nt++) {
                    s1 += acc[mt][nt][0] + acc[mt][nt][1];
                    s2 += acc[mt][nt][2] + acc[mt][nt][3];
                }
                s1 += __shfl_xor_sync(~0u, s1, 1); s1 += __shfl_xor_sync(~0u, s1, 2);
                s2 += __shfl_xor_sync(~0u, s2, 1); s2 += __shfl_xor_sync(~0u, s2, 2);
                const float mu1 = s1 * (1.0f/64.0f), mu2 = s2 * (1.0f/64.0f);
                float v1 = 0.f, v2 = 0.f;
                #pragma unroll
                for (int nt = 0; nt < 8; nt++) {
                    float d0f = acc[mt][nt][0] - mu1, d1f = acc[mt][nt][1] - mu1;
                    float d2f = acc[mt][nt][2] - mu2, d3f = acc[mt][nt][3] - mu2;
                    v1 += d0f*d0f + d1f*d1f;
                    v2 += d2f*d2f + d3f*d3f;
                }
                v1 += __shfl_xor_sync(~0u, v1, 1); v1 += __shfl_xor_sync(~0u, v1, 2);
                v2 += __shfl_xor_sync(~0u, v2, 1); v2 += __shfl_xor_sync(~0u, v2, 2);
                const float iv1 = rsqrtf(v1*(1.0f/64.0f) + 1e-5f);
                const float iv2 = rsqrtf(v2*(1.0f/64.0f) + 1e-5f);
                const bool r1 = (n1 >= Pp) && (n1 < N_ - Ll);
                const bool r2 = (n2 >= Pp) && (n2 < N_ - Ll);

                #pragma unroll
                for (int nt = 0; nt < 8; nt++) {
                    const int col  = nt*8 + 2*(lane & 3);
                    const int colp = nt*4 + (lane & 3);
                    float2 w2 = *(const float2*)(lw + col);
                    float2 bb = *(const float2*)(lb + col);
                    float y0 = fmaf((acc[mt][nt][0]-mu1)*iv1, w2.x, bb.x);
                    float y1 = fmaf((acc[mt][nt][1]-mu1)*iv1, w2.y, bb.y);
                    float y2 = fmaf((acc[mt][nt][2]-mu2)*iv2, w2.x, bb.x);
                    float y3 = fmaf((acc[mt][nt][3]-mu2)*iv2, w2.y, bb.y);
                    if (r1) {
                        float rc = cosr[(n1-Pp)*32 + colp], rs = sinr[(n1-Pp)*32 + colp];
                        float t0 = y0*rc - y1*rs, t1 = y0*rs + y1*rc;
                        y0 = t0; y1 = t1;
                    }
                    if (r2) {
                        float rc = cosr[(n2-Pp)*32 + colp], rs = sinr[(n2-Pp)*32 + colp];
                        float t2 = y2*rc - y3*rs, t3 = y2*rs + y3*rc;
                        y2 = t2; y3 = t3;
                    }
                    if (kind == 0) {
                        y0 *= QSC; y1 *= QSC; y2 *= QSC; y3 *= QSC;
                        *(uint32_t*)(Qh + o1 + col) = packhf(y0, y1);
                        *(uint32_t*)(Qh + o2 + col) = packhf(y2, y3);
                    } else {
                        *(uint32_t*)(Kh + o1 + col) = packhf(y0, y1);
                        *(uint32_t*)(Kh + o2 + col) = packhf(y2, y3);
                    }
                }
            }
        }
    }
}

// ================= HMMA flash attention (key-split warps) ==================
// 64 q-rows/CTA. Warp = 16 q-rows x 32 keys: warps (w, w+4) share q-rows and
// split keys -> K/V LDS traffic halves. Fixed-shift softmax (2^(s-13)) makes
// the final merge a pure addition of partial o/li.
#define KTILE2 16384                  // 128 rows x 128 bytes
#define ASTAGE (2*KTILE2)             // Kh,Vh = 32 KB
#define ATT_SMEM (3*ASTAGE)           // 98304

__global__ __launch_bounds__(256, 2)
void attn_mma(const __half* __restrict__ Qh,
              const __half* __restrict__ Kh, const __half* __restrict__ Vh,
              __half* __restrict__ Oh)
{
    extern __shared__ char smem[];
    const uint32_t sb = smem_u32(smem);
    const int tid = threadIdx.x;
    const int wid = tid >> 5, lane = tid & 31;
    const int qw4 = wid & 3;            // q-row group (16 rows)
    const int khalf = wid >> 2;         // key half (0: keys 0-31, 1: 32-63)
    const int b = blockIdx.z, h = blockIdx.y;
    const int q0 = blockIdx.x * 64;
    const size_t base = ((size_t)(b*H_ + h)) * N_;

    ExpC EC; EC.init();

    const int r0 = tid >> 3, u8 = tid & 7;
    const uint32_t d0 = sw128((uint32_t)(r0 * 128 + u8 * 16));
    const __half* pK = Kh + (base + r0) * D_ + u8 * 8;
    const __half* pV = Vh + (base + r0) * D_ + u8 * 8;

    // ---- stage Q tile (64 rows, 8 KB, in stage-0 area) ----
    {
        const __half* pQ = Qh + (base + q0 + r0) * D_ + u8 * 8;
        #pragma unroll
        for (int t = 0; t < 2; t++) {
            uint4 v = *(const uint4*)(pQ + t * 32 * D_);
            *(uint4*)(smem + d0 + t*4096) = v;
        }
    }
    __syncthreads();

    uint32_t qh[4][4];
    {
        const uint32_t offQ = swbase((uint32_t)((qw4*16 + (lane & 15)) * 128)) ^ (lane & 16);
        #pragma unroll
        for (int ks = 0; ks < 4; ks++)
            LDSM4(qh[ks], sb + (offQ ^ (uint32_t)(ks << 5)));
    }
    __syncthreads();   // Q reads done; smem reusable for KV stages

    // LDSM bases for this warp's 32-key half
    uint32_t offK[2], offV[2];
    #pragma unroll
    for (int p = 0; p < 2; p++)
        offK[p] = swbase((uint32_t)((khalf*32 + p*16 + (lane & 7) + ((lane & 16) >> 1)) * 128))
                  ^ ((lane & 8) << 1);
    #pragma unroll
    for (int ds = 0; ds < 2; ds++)
        offV[ds] = swbase((uint32_t)((khalf*32 + ds*16 + (lane & 15)) * 128)) ^ (lane & 16);

    auto issue = [&](int kt) {
        const uint32_t stg = sb + (uint32_t)(kt % 3) * ASTAGE;
        const int koff = kt * 128 * D_;
        const __half* k = pK + koff;
        const __half* v = pV + koff;
        #pragma unroll
        for (int t = 0; t < 4; t++) {
            CP_A16(stg + d0 + t*4096,
                   (u64)__cvta_generic_to_global(k + t * 32 * D_));
            CP_A16(stg + KTILE2 + d0 + t*4096,
                   (u64)__cvta_generic_to_global(v + t * 32 * D_));
        }
    };

    float o[8][4];
    #pragma unroll
    for (int j = 0; j < 8; j++)
        #pragma unroll
        for (int q = 0; q < 4; q++) o[j][q] = 0.f;
    u64 ls0 = 0ull, ls1 = 0ull;            // packed li accumulators

    issue(0); CP_COMMIT();
    issue(1); CP_COMMIT();

    for (int kt = 0; kt < 8; kt++) {
        if (kt == 7) { CP_WAIT0(); } else { CP_WAIT1(); }
        __syncthreads();
        if (kt + 2 < 8) { issue(kt + 2); CP_COMMIT(); }

        const uint32_t stg = sb + (uint32_t)(kt % 3) * ASTAGE;

        #pragma unroll
        for (int sub = 0; sub < 2; sub++) {
            const uint32_t sKh = stg + (uint32_t)sub * 8192;
            const uint32_t sVh = stg + KTILE2 + (uint32_t)sub * 8192;

            // ---- S = Q K^T over this warp's 32 keys ----
            float s[4][4];
            #pragma unroll
            for (int j = 0; j < 4; j++)
                #pragma unroll
                for (int q = 0; q < 4; q++) s[j][q] = 0.f;

            #pragma unroll
            for (int ks = 0; ks < 4; ks++) {
                const uint32_t kx = (uint32_t)(ks << 5);
                uint32_t kh[2][4];
                #pragma unroll
                for (int p = 0; p < 2; p++)
                    LDSM4(kh[p], sKh + (offK[p] ^ kx));
                #pragma unroll
                for (int p = 0; p < 2; p++)
                    #pragma unroll
                    for (int h2 = 0; h2 < 2; h2++) {
                        int nt = 2*p + h2;
                        mma16816(s[nt], qh[ks], kh[p][2*h2], kh[p][2*h2+1]);
                    }
            }

            // ---- prefetch V fragments for ds=0 (hidden by exp work) ----
            uint32_t vh[4][4];
            #pragma unroll
            for (int dj = 0; dj < 4; dj++)
                LDSM4T(vh[dj], sVh + (offV[0] ^ (uint32_t)(dj << 5)));

            // ---- fixed-shift softmax: p = 2^(s - 13), accumulate li ----
            #pragma unroll
            for (int nt = 0; nt < 4; nt++) {
                u64 e0 = exp2s13x2(pk2(s[nt][0], s[nt][1]), EC);
                u64 e1 = exp2s13x2(pk2(s[nt][2], s[nt][3]), EC);
                upk2(e0, s[nt][0], s[nt][1]);
                upk2(e1, s[nt][2], s[nt][3]);
                ADD2(ls0, ls0, e0);
                ADD2(ls1, ls1, e1);
            }

            // ---- O += P V over 32 keys (2 k-steps), V pipelined ----
            #pragma unroll
            for (int ds = 0; ds < 2; ds++) {
                uint32_t ph[4];
                #pragma unroll
                for (int half = 0; half < 2; half++) {
                    int nt = 2*ds + half;
                    ph[2*half]   = packhf(s[nt][0], s[nt][1]);
                    ph[2*half+1] = packhf(s[nt][2], s[nt][3]);
                }
                uint32_t vhn[4][4];
                if (ds == 0) {
                    #pragma unroll
                    for (int dj = 0; dj < 4; dj++)
                        LDSM4T(vhn[dj], sVh + (offV[1] ^ (uint32_t)(dj << 5)));
                }
                #pragma unroll
                for (int dj = 0; dj < 4; dj++)
                    #pragma unroll
                    for (int h2 = 0; h2 < 2; h2++) {
                        int dt = 2*dj + h2;
                        mma16816(o[dt], ph, vh[dj][2*h2], vh[dj][2*h2+1]);
                    }
                if (ds == 0) {
                    #pragma unroll
                    for (int dj = 0; dj < 4; dj++)
                        #pragma unroll
                        for (int q = 0; q < 4; q++)
                            vh[dj][q] = vhn[dj][q];
                }
            }
        }
    }

    // ---- merge key-half partials (pure addition; fixed-max softmax) ----
    __syncthreads();                       // all stage reads done
    float* mf = (float*)smem;              // reuse stage-0 area (~18 KB)
    if (khalf == 1) {
        float* dst = mf + (size_t)((qw4*32 + lane) * 35);
        #pragma unroll
        for (int dt = 0; dt < 8; dt++)
            #pragma unroll
            for (int q = 0; q < 4; q++)
                dst[dt*4 + q] = o[dt][q];
        float la, lb2;
        upk2(ls0, la, lb2); dst[32] = la + lb2;
        upk2(ls1, la, lb2); dst[33] = la + lb2;
    }
    __syncthreads();
    if (khalf == 0) {
        const float* src = mf + (size_t)((qw4*32 + lane) * 35);
        #pragma unroll
        for (int dt = 0; dt < 8; dt++)
            #pragma unroll
            for (int q = 0; q < 4; q++)
                o[dt][q] += src[dt*4 + q];
        float la, lb2;
        upk2(ls0, la, lb2);
        float li0 = la + lb2 + src[32];
        upk2(ls1, la, lb2);
        float li1 = la + lb2 + src[33];
        li0 += __shfl_xor_sync(~0u, li0, 1);
        li0 += __shfl_xor_sync(~0u, li0, 2);
        li1 += __shfl_xor_sync(~0u, li1, 1);
        li1 += __shfl_xor_sync(~0u, li1, 2);
        const float inv1 = 1.0f / li0;
        const float inv2 = 1.0f / li1;
        const int row1 = q0 + qw4*16 + (lane >> 2);
        #pragma unroll
        for (int dt = 0; dt < 8; dt++) {
            int col = h*D_ + dt*8 + 2*(lane & 3);
            size_t i1 = (size_t)(b*N_ + row1) * C_ + col;
            size_t i2 = (size_t)(b*N_ + row1 + 8) * C_ + col;
            *(uint32_t*)(Oh + i1) = packhf(o[dt][0]*inv1, o[dt][1]*inv1);
            *(uint32_t*)(Oh + i2) = packhf(o[dt][2]*inv2, o[dt][3]*inv2);
        }
    }
}

// ================= launch =================
extern "C" void kernel_launch(void* const* d_in, const int* in_sizes, int n_in,
                              void* d_out, int out_size)
{
    const float* x      = (const float*)d_in[0];
    const float* cosr   = (const float*)d_in[1];
    const float* sinr   = (const float*)d_in[2];
    const float* w_qkv  = (const float*)d_in[3];
    const float* q_ln_w = (const float*)d_in[4];
    const float* q_ln_b = (const float*)d_in[5];
    const float* k_ln_w = (const float*)d_in[6];
    const float* k_ln_b = (const float*)d_in[7];
    const float* w_proj = (const float*)d_in[8];
    const float* b_proj = (const float*)d_in[9];
    const int*   pP     = (const int*)d_in[10];
    const int*   pL     = (const int*)d_in[11];
    float* out = (float*)d_out;

    __half *xh, *wqh, *wph, *qh, *kh, *vh, *oh;
    cudaGetSymbolAddress((void**)&xh,  g_xh);
    cudaGetSymbolAddress((void**)&wqh, g_wqh);
    cudaGetSymbolAddress((void**)&wph, g_wph);
    cudaGetSymbolAddress((void**)&qh,  g_qh);
    cudaGetSymbolAddress((void**)&kh,  g_kh);
    cudaGetSymbolAddress((void**)&vh,  g_vh);
    cudaGetSymbolAddress((void**)&oh,  g_oh);

    cudaFuncSetAttribute(gemm_mma<false>, cudaFuncAttributeMaxDynamicSharedMemorySize, GEMM_SMEM);
    cudaFuncSetAttribute(gemm_mma<true>,  cudaFuncAttributeMaxDynamicSharedMemorySize, GEMM_SMEM);
    cudaFuncSetAttribute(attn_mma, cudaFuncAttributeMaxDynamicSharedMemorySize, ATT_SMEM);

    // 0) fused prep: x round + both weight transposes
    prep_all<<<XBLK + 1728 + 576, 256>>>((const float4*)x, xh,
                                         w_qkv, wqh, w_proj, wph);

    // 1) QKV projection with fused LN+RoPE epilogue -> fp16 Q/K/V
    gemm_mma<true><<<dim3(QKV_/128, M_/128), 256, GEMM_SMEM>>>(
        xh, wqh, nullptr, M_, QKV_, C_, nullptr,
        cosr, sinr, q_ln_w, q_ln_b, k_ln_w, k_ln_b, pP, pL,
        qh, kh, vh);

    // 2) attention (key-split warps) -> fp16 [B,N,C]
    attn_mma<<<dim3(N_/64, H_, B_), 256, ATT_SMEM>>>(qh, kh, vh, oh);

    // 3) output projection + bias
    gemm_mma<false><<<dim3(C_/128, M_/128), 256, GEMM_SMEM>>>(
        oh, wph, out, M_, C_, C_, b_proj,
        nullptr, nullptr, nullptr, nullptr, nullptr, nullptr, nullptr, nullptr,
        nullptr, nullptr, nullptr);
}